// round 12
// baseline (speedup 1.0000x reference)
#include <cuda_runtime.h>
#include <cuda_bf16.h>
#include <math.h>

#define BB 64
#define TT 256
#define EE 300
#define HH 512
#define GG 1536               // 3*H
#define MM (BB*TT)            // 16384

// ---------------- scratch (static device allocations only) ----------------
__device__ __align__(256) float g_xp[2 * MM * GG];       // input projections [dir][B*T, 1536]
__device__ __align__(256) __nv_bfloat16 g_hA[2][2][BB][1024]; // h split [buf][dir][b][hi|lo]
__device__ __align__(256) float g_pooled[BB * 2 * HH];   // maxpool [B, 1024]
__device__ __align__(256) float g_hid[BB * 128];         // mlp hidden
__device__ __align__(256) __nv_bfloat16 g_a3[MM * 3 * 1024];        // split A [M, 3*Kp]
__device__ __align__(256) __nv_bfloat16 g_w3[2 * GG * 3 * 1024];    // split W [2N, 3*Kp]
__device__ unsigned g_bar4[4];

// ---------------- init ----------------
__global__ void init_kernel() {
    const int n = 2 * 2 * BB * 1024 / 2;
    unsigned* p = reinterpret_cast<unsigned*>(&g_hA[0][0][0][0]);
    for (int i = blockIdx.x * blockDim.x + threadIdx.x; i < n; i += gridDim.x * blockDim.x)
        p[i] = 0u;
    if (blockIdx.x == 0 && threadIdx.x < 4) g_bar4[threadIdx.x] = 0u;
}

// ---------------- fused embedding gather + bf16 split (A slabs [hi|hi|lo], Kp=320) ----------------
__global__ void embed_split_kernel(const int* __restrict__ x, const float* __restrict__ emb) {
    const int tok = blockIdx.x;
    const int row = x[tok];
    const int pi = threadIdx.x;          // pair index 0..159
    const int k0 = pi * 2;
    const float v0 = (k0     < EE) ? emb[(size_t)row * EE + k0]     : 0.f;
    const float v1 = (k0 + 1 < EE) ? emb[(size_t)row * EE + k0 + 1] : 0.f;
    const __nv_bfloat16 h0 = __float2bfloat16(v0), h1 = __float2bfloat16(v1);
    const __nv_bfloat16 l0 = __float2bfloat16(v0 - __bfloat162float(h0));
    const __nv_bfloat16 l1 = __float2bfloat16(v1 - __bfloat162float(h1));
    const __nv_bfloat162 hh = __halves2bfloat162(h0, h1);
    const __nv_bfloat162 ll = __halves2bfloat162(l0, l1);
    __nv_bfloat162* d = reinterpret_cast<__nv_bfloat162*>(g_a3 + (size_t)tok * 960);
    d[pi] = hh; d[pi + 160] = hh; d[pi + 320] = ll;
}

// ---------------- bf16 split conversion (weights) ----------------
__global__ void conv_split_kernel(const float* __restrict__ src, __nv_bfloat16* __restrict__ dst,
                                  int rows, int Ksrc, int Kp, int mode) {
    const long i = (long)blockIdx.x * blockDim.x + threadIdx.x;
    const long total = (long)rows * (Kp / 2);
    if (i >= total) return;
    const int m  = (int)(i / (Kp / 2));
    const int k0 = (int)(i % (Kp / 2)) * 2;
    const float v0 = (k0     < Ksrc) ? src[(size_t)m * Ksrc + k0]     : 0.f;
    const float v1 = (k0 + 1 < Ksrc) ? src[(size_t)m * Ksrc + k0 + 1] : 0.f;
    const __nv_bfloat16 h0 = __float2bfloat16(v0), h1 = __float2bfloat16(v1);
    const __nv_bfloat16 l0 = __float2bfloat16(v0 - __bfloat162float(h0));
    const __nv_bfloat16 l1 = __float2bfloat16(v1 - __bfloat162float(h1));
    const __nv_bfloat162 hh = __halves2bfloat162(h0, h1);
    const __nv_bfloat162 ll = __halves2bfloat162(l0, l1);
    __nv_bfloat162* d = reinterpret_cast<__nv_bfloat162*>(dst + (size_t)m * 3 * Kp);
    const int p = k0 >> 1, s = Kp >> 1;
    if (mode == 0) { d[p] = hh; d[p + s] = hh; d[p + 2 * s] = ll; }
    else           { d[p] = hh; d[p + s] = ll; d[p + 2 * s] = hh; }
}

// ---------------- bf16 tensor-core GEMM, 4-stage cp.async pipeline ----------------
#define PKH 40
__global__ void __launch_bounds__(256, 2) bgemm_kernel(
    const __nv_bfloat16* __restrict__ A, const __nv_bfloat16* __restrict__ W,
    const float* __restrict__ bias, float* __restrict__ C, int M, int N, int K3)
{
    extern __shared__ __nv_bfloat16 gsm[];
    __nv_bfloat16* As = gsm;                    // [4][128*PKH]
    __nv_bfloat16* Bs = gsm + 4 * 128 * PKH;    // [4][128*PKH]

    const int z = blockIdx.z;
    W    += (size_t)z * N * K3;
    bias += (size_t)z * N;
    C    += (size_t)z * M * N;

    const int m0 = blockIdx.y * 128, n0 = blockIdx.x * 128;
    const int tid = threadIdx.x;
    const int warp = tid >> 5, lane = tid & 31;
    const int wm = warp >> 2, wn = warp & 3;

    float c[4][4][4];
#pragma unroll
    for (int mi = 0; mi < 4; mi++)
#pragma unroll
        for (int ni = 0; ni < 4; ni++)
#pragma unroll
            for (int q = 0; q < 4; q++) c[mi][ni][q] = 0.f;

    const int lrow = tid >> 2;
    const int lcol = (tid & 3) * 8;
    const unsigned asb = (unsigned)__cvta_generic_to_shared(As);
    const unsigned bsb = (unsigned)__cvta_generic_to_shared(Bs);
    const int nk = K3 / 32;

#define BG_ISSUE(KT, BUF) do {                                                        \
        const int kg_ = (KT) * 32 + lcol;                                             \
        const size_t ar_ = (size_t)(m0 + lrow) * K3 + kg_;                            \
        const size_t br_ = (size_t)(n0 + lrow) * K3 + kg_;                            \
        const unsigned ao_ = (unsigned)((((BUF) * 128 + lrow) * PKH + lcol) << 1);    \
        asm volatile("cp.async.cg.shared.global [%0],[%1],16;"                        \
            :: "r"(asb + ao_), "l"(A + ar_) : "memory");                              \
        asm volatile("cp.async.cg.shared.global [%0],[%1],16;"                        \
            :: "r"(asb + ao_ + (unsigned)((64 * PKH) << 1)), "l"(A + ar_ + (size_t)64 * K3) : "memory"); \
        asm volatile("cp.async.cg.shared.global [%0],[%1],16;"                        \
            :: "r"(bsb + ao_), "l"(W + br_) : "memory");                              \
        asm volatile("cp.async.cg.shared.global [%0],[%1],16;"                        \
            :: "r"(bsb + ao_ + (unsigned)((64 * PKH) << 1)), "l"(W + br_ + (size_t)64 * K3) : "memory"); \
        asm volatile("cp.async.commit_group;" ::: "memory");                          \
    } while (0)

    BG_ISSUE(0, 0);
    if (nk > 1) BG_ISSUE(1, 1);
    if (nk > 2) BG_ISSUE(2, 2);

    for (int kt = 0; kt < nk; kt++) {
        if (kt + 2 < nk)      asm volatile("cp.async.wait_group 2;" ::: "memory");
        else if (kt + 1 < nk) asm volatile("cp.async.wait_group 1;" ::: "memory");
        else                  asm volatile("cp.async.wait_group 0;" ::: "memory");
        __syncthreads();
        if (kt + 3 < nk) BG_ISSUE(kt + 3, (kt + 3) & 3);

        const unsigned abase = asb + (unsigned)(((kt & 3) * 128 * PKH) << 1);
        const unsigned bbase = bsb + (unsigned)(((kt & 3) * 128 * PKH) << 1);

#pragma unroll
        for (int kk = 0; kk < 32; kk += 16) {
            unsigned a[4][4], b[4][2];
#pragma unroll
            for (int mi = 0; mi < 4; mi++) {
                const unsigned ad = abase +
                    (((wm * 64 + mi * 16 + (lane & 15)) * PKH + kk + (lane >> 4) * 8) << 1);
                asm volatile("ldmatrix.sync.aligned.m8n8.x4.shared.b16 {%0,%1,%2,%3}, [%4];"
                    : "=r"(a[mi][0]), "=r"(a[mi][1]), "=r"(a[mi][2]), "=r"(a[mi][3]) : "r"(ad));
            }
#pragma unroll
            for (int nj = 0; nj < 2; nj++) {
                const int g = lane >> 3, rr = lane & 7;
                const unsigned bd = bbase +
                    (((wn * 32 + nj * 16 + (g >> 1) * 8 + rr) * PKH + kk + (g & 1) * 8) << 1);
                asm volatile("ldmatrix.sync.aligned.m8n8.x4.shared.b16 {%0,%1,%2,%3}, [%4];"
                    : "=r"(b[nj * 2][0]), "=r"(b[nj * 2][1]),
                      "=r"(b[nj * 2 + 1][0]), "=r"(b[nj * 2 + 1][1]) : "r"(bd));
            }
#pragma unroll
            for (int mi = 0; mi < 4; mi++)
#pragma unroll
                for (int ni = 0; ni < 4; ni++)
                    asm volatile(
                        "mma.sync.aligned.m16n8k16.row.col.f32.bf16.bf16.f32 "
                        "{%0,%1,%2,%3}, {%4,%5,%6,%7}, {%8,%9}, {%0,%1,%2,%3};"
                        : "+f"(c[mi][ni][0]), "+f"(c[mi][ni][1]),
                          "+f"(c[mi][ni][2]), "+f"(c[mi][ni][3])
                        : "r"(a[mi][0]), "r"(a[mi][1]), "r"(a[mi][2]), "r"(a[mi][3]),
                          "r"(b[ni][0]), "r"(b[ni][1]));
        }
    }

#pragma unroll
    for (int mi = 0; mi < 4; mi++) {
        const int row = m0 + wm * 64 + mi * 16 + (lane >> 2);
#pragma unroll
        for (int ni = 0; ni < 4; ni++) {
            const int col = n0 + wn * 32 + ni * 8 + (lane & 3) * 2;
            const float bx = bias[col], by = bias[col + 1];
            float2 v0 = make_float2(c[mi][ni][0] + bx, c[mi][ni][1] + by);
            float2 v1 = make_float2(c[mi][ni][2] + bx, c[mi][ni][3] + by);
            *reinterpret_cast<float2*>(&C[(size_t)row * N + col]) = v0;
            *reinterpret_cast<float2*>(&C[(size_t)(row + 8) * N + col]) = v1;
        }
    }
}

__device__ __forceinline__ float fast_sig(float x) {
    return __fdividef(1.f, 1.f + __expf(-x));
}
__device__ __forceinline__ float fast_tanh(float x) {
    return 1.f - __fdividef(2.f, __expf(2.f * x) + 1.f);
}

// ---------------- tensor-core persistent BiGRU recurrence ----------------
// 128 CTAs: dir = cta>>6, ks = (cta&63)>>1 (16 k-cols), bg = cta&1 (32 batches).
// Arrive/wait split barrier (known-good sync structure).
// Whi fragments fully register-cached; Wlo cached for iters 0..7.
// Epilogue parallelized over ALL 256 threads: each k-half group stores the
// accumulator quads it does NOT own (kh0 -> q2/q3, kh1 -> q0/q1); every thread
// then finishes exactly 2 cells (kh0 rows +0, kh1 rows +8).
#define PA 1032   // A smem pitch (halves)
#define PW 520    // W smem pitch (halves)
__global__ void __launch_bounds__(256, 1) recur_tc_kernel(
    const float* __restrict__ xp,    // [dir][B*T, 1536] (includes b_ih)
    const float* __restrict__ w_hh,  // [2][1536][512]
    const float* __restrict__ b_hh,  // [2][1536]
    __nv_bfloat16* __restrict__ a3,  // layer-1 split A out [M, 3*1024] or nullptr
    int do_pool)
{
    extern __shared__ char smraw[];
    __nv_bfloat16* sWhi = reinterpret_cast<__nv_bfloat16*>(smraw);   // [48][PW]
    __nv_bfloat16* sWlo = sWhi + 48 * PW;                             // [48][PW]
    __nv_bfloat16* sA   = sWlo + 48 * PW;                             // [32][PA]
    float* sred  = reinterpret_cast<float*>(sA + 32 * PA);            // [128][13]

    const int cta = blockIdx.x;
    const int dir = cta >> 6;
    const int ks  = (cta & 63) >> 1;
    const int bg  = cta & 1;
    const int k0  = ks * 16;
    const int tid = threadIdx.x;
    const int warp = tid >> 5, lane = tid & 31;
    const int kh = warp >> 2;
    const int wm = (warp >> 1) & 1;
    const int wn = warp & 1;
    unsigned* bar = &g_bar4[dir * 2 + bg];

    // ---- load + split W_hh slice, rows ordered [blk(2)][gate(3)][kcl(8)]
    {
        const float* wsrc = w_hh + (size_t)dir * GG * HH;
        for (int idx = tid; idx < 48 * 128; idx += 256) {
            const int jj = idx >> 7;
            const int q  = (idx & 127) * 4;
            const int blk = jj / 24, within = jj % 24;
            const int gate = within >> 3, kcl = within & 7;
            const int grow = gate * HH + k0 + blk * 8 + kcl;
            const float4 v = *reinterpret_cast<const float4*>(&wsrc[(size_t)grow * HH + q]);
            const __nv_bfloat16 h0 = __float2bfloat16(v.x), h1 = __float2bfloat16(v.y);
            const __nv_bfloat16 h2 = __float2bfloat16(v.z), h3 = __float2bfloat16(v.w);
            const __nv_bfloat16 l0 = __float2bfloat16(v.x - __bfloat162float(h0));
            const __nv_bfloat16 l1 = __float2bfloat16(v.y - __bfloat162float(h1));
            const __nv_bfloat16 l2 = __float2bfloat16(v.z - __bfloat162float(h2));
            const __nv_bfloat16 l3 = __float2bfloat16(v.w - __bfloat162float(h3));
            __nv_bfloat162* dh = reinterpret_cast<__nv_bfloat162*>(sWhi + jj * PW + q);
            __nv_bfloat162* dl = reinterpret_cast<__nv_bfloat162*>(sWlo + jj * PW + q);
            dh[0] = __halves2bfloat162(h0, h1); dh[1] = __halves2bfloat162(h2, h3);
            dl[0] = __halves2bfloat162(l0, l1); dl[1] = __halves2bfloat162(l2, l3);
        }
    }

    // epilogue cell ownership: every thread owns 1 row x 2 cols
    const int r0e = wm * 16 + (lane >> 2) + kh * 8;   // owned batch row (0..31)
    const int kc2 = wn * 8 + (lane & 3) * 2;          // owned col pair
    const int brow = bg * 32 + r0e;
    const float br0 = b_hh[dir * GG + 0 * HH + k0 + kc2];
    const float br1 = b_hh[dir * GG + 0 * HH + k0 + kc2 + 1];
    const float bz0 = b_hh[dir * GG + 1 * HH + k0 + kc2];
    const float bz1 = b_hh[dir * GG + 1 * HH + k0 + kc2 + 1];
    const float bn0 = b_hh[dir * GG + 2 * HH + k0 + kc2];
    const float bn1 = b_hh[dir * GG + 2 * HH + k0 + kc2 + 1];
    float hprev[2] = {0.f, 0.f};
    float mx[2] = {-1e30f, -1e30f};
    unsigned bar_tgt = 0;
    __syncthreads();

    const unsigned sAb  = (unsigned)__cvta_generic_to_shared(sA);
    const unsigned sWhb = (unsigned)__cvta_generic_to_shared(sWhi);
    const unsigned sWlb = (unsigned)__cvta_generic_to_shared(sWlo);
    const int t128 = tid & 127;

    // ---- preload loop-invariant W fragments: Whi (all 16 iters), Wlo (iters 0..7)
    unsigned wf[16][6];
    unsigned wl[8][6];
    {
        const int g_ = lane >> 3, rr_ = lane & 7;
#pragma unroll
        for (int i = 0; i < 16; i++) {
            const int kk = kh * 256 + i * 16;
            const unsigned bo  = (unsigned)(((wn * 24 + (g_ >> 1) * 8 + rr_) * PW + kk + (g_ & 1) * 8) << 1);
            const unsigned bo2 = (unsigned)(((wn * 24 + 16 + rr_) * PW + kk + ((lane >> 3) & 1) * 8) << 1);
            asm volatile("ldmatrix.sync.aligned.m8n8.x4.shared.b16 {%0,%1,%2,%3}, [%4];"
                : "=r"(wf[i][0]), "=r"(wf[i][1]), "=r"(wf[i][2]), "=r"(wf[i][3]) : "r"(sWhb + bo));
            asm volatile("ldmatrix.sync.aligned.m8n8.x2.shared.b16 {%0,%1}, [%2];"
                : "=r"(wf[i][4]), "=r"(wf[i][5]) : "r"(sWhb + bo2));
            if (i < 8) {
                asm volatile("ldmatrix.sync.aligned.m8n8.x4.shared.b16 {%0,%1,%2,%3}, [%4];"
                    : "=r"(wl[i][0]), "=r"(wl[i][1]), "=r"(wl[i][2]), "=r"(wl[i][3]) : "r"(sWlb + bo));
                asm volatile("ldmatrix.sync.aligned.m8n8.x2.shared.b16 {%0,%1}, [%2];"
                    : "=r"(wl[i][4]), "=r"(wl[i][5]) : "r"(sWlb + bo2));
            }
        }
    }

    for (int s = 0; s < TT; s++) {
        const int t = dir ? (TT - 1 - s) : s;
        const int p = s & 1;

        // ---- spin-window work: prefetch this thread's xp operands (all threads)
        const size_t xb = ((size_t)(dir * BB + brow) * TT + t) * GG + k0 + kc2;
        const float2 xr = __ldg(reinterpret_cast<const float2*>(xp + xb));
        const float2 xz = __ldg(reinterpret_cast<const float2*>(xp + xb + HH));
        const float2 xn = __ldg(reinterpret_cast<const float2*>(xp + xb + 2 * HH));

        // ---- wait for step-s h (counter >= 32*s)
        if (tid == 0 && s > 0) {
            unsigned v;
            do {
                asm volatile("ld.acquire.gpu.global.u32 %0, [%1];"
                             : "=r"(v) : "l"(bar) : "memory");
            } while (v < bar_tgt);
        }
        __syncthreads();

        // ---- issue own-group h chunks: hi (cols kh*256), then lo (512+kh*256)
        {
            const __nv_bfloat16* hsrc = &g_hA[p][dir][bg * 32][0];
#pragma unroll
            for (int it = 0; it < 8; it++) {
                const int idx = it * 128 + t128;
                const int row = idx >> 5, seg = idx & 31;
                const int col = kh * 256 + seg * 8;
                asm volatile("cp.async.cg.shared.global [%0], [%1], 16;"
                    :: "r"(sAb + (unsigned)((row * PA + col) << 1)),
                       "l"(hsrc + row * 1024 + col) : "memory");
            }
            asm volatile("cp.async.commit_group;" ::: "memory");
#pragma unroll
            for (int it = 0; it < 8; it++) {
                const int idx = it * 128 + t128;
                const int row = idx >> 5, seg = idx & 31;
                const int col = 512 + kh * 256 + seg * 8;
                asm volatile("cp.async.cg.shared.global [%0], [%1], 16;"
                    :: "r"(sAb + (unsigned)((row * PA + col) << 1)),
                       "l"(hsrc + row * 1024 + col) : "memory");
            }
            asm volatile("cp.async.commit_group;" ::: "memory");
        }

        float c0[4] = {0.f, 0.f, 0.f, 0.f};
        float c1[4] = {0.f, 0.f, 0.f, 0.f};
        float c2[4] = {0.f, 0.f, 0.f, 0.f};

        // ---- phase A: hi chunk ready -> a_hi x (Whi[regs], Wlo[regs 0..7 / smem 8..15])
        asm volatile("cp.async.wait_group 1;" ::: "memory");
        asm volatile("bar.sync %0, 128;" :: "r"(1 + kh) : "memory");
#pragma unroll
        for (int i = 0; i < 16; i++) {
            const int kk = kh * 256 + i * 16;
            unsigned a0, a1, a2, a3r;
            const unsigned ad = sAb + ((((wm * 16 + (lane & 15)) * PA) + kk + (lane >> 4) * 8) << 1);
            asm volatile("ldmatrix.sync.aligned.m8n8.x4.shared.b16 {%0,%1,%2,%3}, [%4];"
                : "=r"(a0), "=r"(a1), "=r"(a2), "=r"(a3r) : "r"(ad));
#define MMA1(CC, B0, B1) \
            asm volatile("mma.sync.aligned.m16n8k16.row.col.f32.bf16.bf16.f32 " \
                "{%0,%1,%2,%3}, {%4,%5,%6,%7}, {%8,%9}, {%0,%1,%2,%3};" \
                : "+f"(CC[0]), "+f"(CC[1]), "+f"(CC[2]), "+f"(CC[3]) \
                : "r"(a0), "r"(a1), "r"(a2), "r"(a3r), "r"(B0), "r"(B1))
            MMA1(c0, wf[i][0], wf[i][1]); MMA1(c1, wf[i][2], wf[i][3]); MMA1(c2, wf[i][4], wf[i][5]);
            if (i < 8) {
                MMA1(c0, wl[i][0], wl[i][1]); MMA1(c1, wl[i][2], wl[i][3]); MMA1(c2, wl[i][4], wl[i][5]);
            } else {
                unsigned l00, l01, l10, l11, l20, l21;
                const int g_ = lane >> 3, rr_ = lane & 7;
                const unsigned bo  = (unsigned)(((wn * 24 + (g_ >> 1) * 8 + rr_) * PW + kk + (g_ & 1) * 8) << 1);
                const unsigned bo2 = (unsigned)(((wn * 24 + 16 + rr_) * PW + kk + ((lane >> 3) & 1) * 8) << 1);
                asm volatile("ldmatrix.sync.aligned.m8n8.x4.shared.b16 {%0,%1,%2,%3}, [%4];"
                    : "=r"(l00), "=r"(l01), "=r"(l10), "=r"(l11) : "r"(sWlb + bo));
                asm volatile("ldmatrix.sync.aligned.m8n8.x2.shared.b16 {%0,%1}, [%2];"
                    : "=r"(l20), "=r"(l21) : "r"(sWlb + bo2));
                MMA1(c0, l00, l01); MMA1(c1, l10, l11); MMA1(c2, l20, l21);
            }
        }

        // ---- phase B: lo chunk ready -> a_lo x Whi[regs]
        asm volatile("cp.async.wait_group 0;" ::: "memory");
        asm volatile("bar.sync %0, 128;" :: "r"(1 + kh) : "memory");
#pragma unroll
        for (int i = 0; i < 16; i++) {
            const int kk = kh * 256 + i * 16;
            unsigned a0, a1, a2, a3r;
            const unsigned ad = sAb + ((((wm * 16 + (lane & 15)) * PA) + 512 + kk + (lane >> 4) * 8) << 1);
            asm volatile("ldmatrix.sync.aligned.m8n8.x4.shared.b16 {%0,%1,%2,%3}, [%4];"
                : "=r"(a0), "=r"(a1), "=r"(a2), "=r"(a3r) : "r"(ad));
            MMA1(c0, wf[i][0], wf[i][1]); MMA1(c1, wf[i][2], wf[i][3]); MMA1(c2, wf[i][4], wf[i][5]);
        }

        // ---- symmetric exchange: store the quads this group does NOT own
        {
            float* rp = sred + (size_t)t128 * 13;
            if (kh == 0) {
                rp[0] = c0[2]; rp[1] = c0[3]; rp[2] = c1[2];
                rp[3] = c1[3]; rp[4] = c2[2]; rp[5] = c2[3];
            } else {
                rp[6] = c0[0]; rp[7] = c0[1]; rp[8] = c1[0];
                rp[9] = c1[1]; rp[10] = c2[0]; rp[11] = c2[1];
            }
        }
        __syncthreads();

        // ---- epilogue: every thread finishes its 2 owned cells
        float hv[2];
        __nv_bfloat162 hp2, lp2;
        {
            const float* rp = sred + (size_t)t128 * 13 + (kh ? 0 : 6);
            const int qa = kh * 2;
            const float g0r = c0[qa]     + rp[0] + br0;
            const float g1r = c0[qa + 1] + rp[1] + br1;
            const float g0z = c1[qa]     + rp[2] + bz0;
            const float g1z = c1[qa + 1] + rp[3] + bz1;
            const float g0n = c2[qa]     + rp[4] + bn0;
            const float g1n = c2[qa + 1] + rp[5] + bn1;
            const float rg0 = fast_sig(xr.x + g0r);
            const float rg1 = fast_sig(xr.y + g1r);
            const float zg0 = fast_sig(xz.x + g0z);
            const float zg1 = fast_sig(xz.y + g1z);
            const float ng0 = fast_tanh(xn.x + rg0 * g0n);
            const float ng1 = fast_tanh(xn.y + rg1 * g1n);
            hv[0] = (1.f - zg0) * ng0 + zg0 * hprev[0];
            hv[1] = (1.f - zg1) * ng1 + zg1 * hprev[1];
            hprev[0] = hv[0]; hprev[1] = hv[1];
            const __nv_bfloat16 h0 = __float2bfloat16(hv[0]);
            const __nv_bfloat16 h1 = __float2bfloat16(hv[1]);
            const __nv_bfloat16 l0 = __float2bfloat16(hv[0] - __bfloat162float(h0));
            const __nv_bfloat16 l1 = __float2bfloat16(hv[1] - __bfloat162float(h1));
            hp2 = __halves2bfloat162(h0, h1);
            lp2 = __halves2bfloat162(l0, l1);
            __nv_bfloat16* dst = &g_hA[1 - p][dir][brow][k0 + kc2];
            __stcg(reinterpret_cast<unsigned*>(dst),
                   *reinterpret_cast<const unsigned*>(&hp2));
            __stcg(reinterpret_cast<unsigned*>(dst + 512),
                   *reinterpret_cast<const unsigned*>(&lp2));
        }
        __syncthreads();
        // ---- arrive (release h stores), then deferred output work in spin window
        bar_tgt += 32u;
        if (tid == 0) {
            unsigned prev;
            asm volatile("atom.acq_rel.gpu.global.add.u32 %0, [%1], 1;"
                         : "=r"(prev) : "l"(bar) : "memory");
            (void)prev;
        }
        if (do_pool) {
            mx[0] = fmaxf(mx[0], hv[0]);
            mx[1] = fmaxf(mx[1], hv[1]);
        }
        if (a3) {
            __nv_bfloat16* ad3 = a3 + ((size_t)brow * TT + t) * 3072 + dir * HH + k0 + kc2;
            *reinterpret_cast<unsigned*>(ad3)        = *reinterpret_cast<const unsigned*>(&hp2);
            *reinterpret_cast<unsigned*>(ad3 + 1024) = *reinterpret_cast<const unsigned*>(&hp2);
            *reinterpret_cast<unsigned*>(ad3 + 2048) = *reinterpret_cast<const unsigned*>(&lp2);
        }
    }

    if (do_pool) {
        g_pooled[(size_t)brow * (2 * HH) + dir * HH + k0 + kc2]     = mx[0];
        g_pooled[(size_t)brow * (2 * HH) + dir * HH + k0 + kc2 + 1] = mx[1];
    }
}

// ---------------- classifier head ----------------
__global__ void mlp1_kernel(const float* __restrict__ w1, const float* __restrict__ b1) {
    const int warp = (blockIdx.x * blockDim.x + threadIdx.x) >> 5;
    const int lane = threadIdx.x & 31;
    if (warp >= BB * 128) return;
    const int b = warp >> 7, j = warp & 127;
    const float* p = g_pooled + (size_t)b * 2 * HH;
    const float* w = w1 + (size_t)j * 2 * HH;
    float s = 0.f;
    for (int k = lane; k < 2 * HH; k += 32) s = fmaf(p[k], w[k], s);
#pragma unroll
    for (int o = 16; o; o >>= 1) s += __shfl_xor_sync(0xffffffffu, s, o);
    if (lane == 0) g_hid[b * 128 + j] = fmaxf(s + b1[j], 0.f);
}

__global__ void mlp2_kernel(const float* __restrict__ w2, const float* __restrict__ b2,
                            float* __restrict__ out) {
    const int t = threadIdx.x;
    if (t < BB * 2) {
        const int b = t >> 1, c = t & 1;
        float s = b2[c];
        const float* h = g_hid + b * 128;
        const float* w = w2 + c * 128;
        for (int k = 0; k < 128; k++) s = fmaf(h[k], w[k], s);
        out[t] = s;
    }
}

// ---------------- launch ----------------
extern "C" void kernel_launch(void* const* d_in, const int* in_sizes, int n_in,
                              void* d_out, int out_size) {
    const int*   x    = (const int*)d_in[0];
    const float* emb  = (const float*)d_in[1];
    const float* wih0 = (const float*)d_in[2];
    const float* whh0 = (const float*)d_in[3];
    const float* bih0 = (const float*)d_in[4];
    const float* bhh0 = (const float*)d_in[5];
    const float* wih1 = (const float*)d_in[6];
    const float* whh1 = (const float*)d_in[7];
    const float* bih1 = (const float*)d_in[8];
    const float* bhh1 = (const float*)d_in[9];
    const float* w1   = (const float*)d_in[10];
    const float* b1   = (const float*)d_in[11];
    const float* w2   = (const float*)d_in[12];
    const float* b2   = (const float*)d_in[13];

    float* xp_p = nullptr;
    __nv_bfloat16 *a3_p = nullptr, *w3_p = nullptr;
    cudaGetSymbolAddress((void**)&xp_p, g_xp);
    cudaGetSymbolAddress((void**)&a3_p, g_a3);
    cudaGetSymbolAddress((void**)&w3_p, g_w3);

    const size_t sm_tc = (size_t)(2 * 48 * PW + 32 * PA) * sizeof(__nv_bfloat16)
                       + (size_t)(128 * 13) * sizeof(float);
    cudaFuncSetAttribute(recur_tc_kernel, cudaFuncAttributeMaxDynamicSharedMemorySize, (int)sm_tc);
    const size_t sm_gemm = (size_t)8 * 128 * PKH * sizeof(__nv_bfloat16);
    cudaFuncSetAttribute(bgemm_kernel, cudaFuncAttributeMaxDynamicSharedMemorySize, (int)sm_gemm);

    // ---- layer 0 ----
    init_kernel<<<64, 256>>>();
    embed_split_kernel<<<MM, 160>>>(x, emb);
    {
        const long pw = (long)(2 * GG) * (320 / 2);
        conv_split_kernel<<<(unsigned)((pw + 255) / 256), 256>>>(wih0, w3_p, 2 * GG, EE, 320, 1);
    }
    bgemm_kernel<<<dim3(GG / 128, MM / 128, 2), 256, sm_gemm>>>(a3_p, w3_p, bih0, xp_p, MM, GG, 960);
    // W split for layer 1
    {
        const long pw = (long)(2 * GG) * (1024 / 2);
        conv_split_kernel<<<(unsigned)((pw + 255) / 256), 256>>>(wih1, w3_p, 2 * GG, 2 * HH, 1024, 1);
    }
    recur_tc_kernel<<<128, 256, sm_tc>>>(xp_p, whh0, bhh0, a3_p, 0);  // writes layer-1 split A

    // ---- layer 1 ----
    bgemm_kernel<<<dim3(GG / 128, MM / 128, 2), 256, sm_gemm>>>(a3_p, w3_p, bih1, xp_p, MM, GG, 3072);
    init_kernel<<<64, 256>>>();
    recur_tc_kernel<<<128, 256, sm_tc>>>(xp_p, whh1, bhh1, nullptr, 1);

    // ---- head ----
    mlp1_kernel<<<(BB * 128 * 32) / 256, 256>>>(w1, b1);
    mlp2_kernel<<<1, 128>>>(w2, b2, (float*)d_out);
}

// round 13
// speedup vs baseline: 1.1051x; 1.1051x over previous
#include <cuda_runtime.h>
#include <cuda_bf16.h>
#include <math.h>

#define BB 64
#define TT 256
#define EE 300
#define HH 512
#define GG 1536               // 3*H
#define MM (BB*TT)            // 16384

// ---------------- scratch (static device allocations only) ----------------
__device__ __align__(256) float g_xp[2 * MM * GG];       // input projections [dir][B*T, 1536]
__device__ __align__(256) __nv_bfloat16 g_hA[2][2][BB][1024]; // h split [buf][dir][b][hi|lo]
__device__ __align__(256) float g_pooled[BB * 2 * HH];   // maxpool [B, 1024]
__device__ __align__(256) float g_hid[BB * 128];         // mlp hidden
__device__ __align__(256) __nv_bfloat16 g_a3[MM * 3 * 1024];        // split A [M, 3*Kp]
__device__ __align__(256) __nv_bfloat16 g_w3[2 * GG * 3 * 1024];    // split W [2N, 3*Kp]
__device__ unsigned g_bar4[4];

// ---------------- init ----------------
__global__ void init_kernel() {
    const int n = 2 * 2 * BB * 1024 / 2;
    unsigned* p = reinterpret_cast<unsigned*>(&g_hA[0][0][0][0]);
    for (int i = blockIdx.x * blockDim.x + threadIdx.x; i < n; i += gridDim.x * blockDim.x)
        p[i] = 0u;
    if (blockIdx.x == 0 && threadIdx.x < 4) g_bar4[threadIdx.x] = 0u;
}

// ---------------- fused embedding gather + bf16 split (A slabs [hi|hi|lo], Kp=320) ----------------
__global__ void embed_split_kernel(const int* __restrict__ x, const float* __restrict__ emb) {
    const int tok = blockIdx.x;
    const int row = x[tok];
    const int pi = threadIdx.x;          // pair index 0..159
    const int k0 = pi * 2;
    const float v0 = (k0     < EE) ? emb[(size_t)row * EE + k0]     : 0.f;
    const float v1 = (k0 + 1 < EE) ? emb[(size_t)row * EE + k0 + 1] : 0.f;
    const __nv_bfloat16 h0 = __float2bfloat16(v0), h1 = __float2bfloat16(v1);
    const __nv_bfloat16 l0 = __float2bfloat16(v0 - __bfloat162float(h0));
    const __nv_bfloat16 l1 = __float2bfloat16(v1 - __bfloat162float(h1));
    const __nv_bfloat162 hh = __halves2bfloat162(h0, h1);
    const __nv_bfloat162 ll = __halves2bfloat162(l0, l1);
    __nv_bfloat162* d = reinterpret_cast<__nv_bfloat162*>(g_a3 + (size_t)tok * 960);
    d[pi] = hh; d[pi + 160] = hh; d[pi + 320] = ll;
}

// ---------------- bf16 split conversion (weights) ----------------
__global__ void conv_split_kernel(const float* __restrict__ src, __nv_bfloat16* __restrict__ dst,
                                  int rows, int Ksrc, int Kp, int mode) {
    const long i = (long)blockIdx.x * blockDim.x + threadIdx.x;
    const long total = (long)rows * (Kp / 2);
    if (i >= total) return;
    const int m  = (int)(i / (Kp / 2));
    const int k0 = (int)(i % (Kp / 2)) * 2;
    const float v0 = (k0     < Ksrc) ? src[(size_t)m * Ksrc + k0]     : 0.f;
    const float v1 = (k0 + 1 < Ksrc) ? src[(size_t)m * Ksrc + k0 + 1] : 0.f;
    const __nv_bfloat16 h0 = __float2bfloat16(v0), h1 = __float2bfloat16(v1);
    const __nv_bfloat16 l0 = __float2bfloat16(v0 - __bfloat162float(h0));
    const __nv_bfloat16 l1 = __float2bfloat16(v1 - __bfloat162float(h1));
    const __nv_bfloat162 hh = __halves2bfloat162(h0, h1);
    const __nv_bfloat162 ll = __halves2bfloat162(l0, l1);
    __nv_bfloat162* d = reinterpret_cast<__nv_bfloat162*>(dst + (size_t)m * 3 * Kp);
    const int p = k0 >> 1, s = Kp >> 1;
    if (mode == 0) { d[p] = hh; d[p + s] = hh; d[p + 2 * s] = ll; }
    else           { d[p] = hh; d[p + s] = ll; d[p + 2 * s] = hh; }
}

// ---------------- bf16 tensor-core GEMM, 4-stage cp.async pipeline ----------------
#define PKH 40
__global__ void __launch_bounds__(256, 2) bgemm_kernel(
    const __nv_bfloat16* __restrict__ A, const __nv_bfloat16* __restrict__ W,
    const float* __restrict__ bias, float* __restrict__ C, int M, int N, int K3)
{
    extern __shared__ __nv_bfloat16 gsm[];
    __nv_bfloat16* As = gsm;                    // [4][128*PKH]
    __nv_bfloat16* Bs = gsm + 4 * 128 * PKH;    // [4][128*PKH]

    const int z = blockIdx.z;
    W    += (size_t)z * N * K3;
    bias += (size_t)z * N;
    C    += (size_t)z * M * N;

    const int m0 = blockIdx.y * 128, n0 = blockIdx.x * 128;
    const int tid = threadIdx.x;
    const int warp = tid >> 5, lane = tid & 31;
    const int wm = warp >> 2, wn = warp & 3;

    float c[4][4][4];
#pragma unroll
    for (int mi = 0; mi < 4; mi++)
#pragma unroll
        for (int ni = 0; ni < 4; ni++)
#pragma unroll
            for (int q = 0; q < 4; q++) c[mi][ni][q] = 0.f;

    const int lrow = tid >> 2;
    const int lcol = (tid & 3) * 8;
    const unsigned asb = (unsigned)__cvta_generic_to_shared(As);
    const unsigned bsb = (unsigned)__cvta_generic_to_shared(Bs);
    const int nk = K3 / 32;

#define BG_ISSUE(KT, BUF) do {                                                        \
        const int kg_ = (KT) * 32 + lcol;                                             \
        const size_t ar_ = (size_t)(m0 + lrow) * K3 + kg_;                            \
        const size_t br_ = (size_t)(n0 + lrow) * K3 + kg_;                            \
        const unsigned ao_ = (unsigned)((((BUF) * 128 + lrow) * PKH + lcol) << 1);    \
        asm volatile("cp.async.cg.shared.global [%0],[%1],16;"                        \
            :: "r"(asb + ao_), "l"(A + ar_) : "memory");                              \
        asm volatile("cp.async.cg.shared.global [%0],[%1],16;"                        \
            :: "r"(asb + ao_ + (unsigned)((64 * PKH) << 1)), "l"(A + ar_ + (size_t)64 * K3) : "memory"); \
        asm volatile("cp.async.cg.shared.global [%0],[%1],16;"                        \
            :: "r"(bsb + ao_), "l"(W + br_) : "memory");                              \
        asm volatile("cp.async.cg.shared.global [%0],[%1],16;"                        \
            :: "r"(bsb + ao_ + (unsigned)((64 * PKH) << 1)), "l"(W + br_ + (size_t)64 * K3) : "memory"); \
        asm volatile("cp.async.commit_group;" ::: "memory");                          \
    } while (0)

    BG_ISSUE(0, 0);
    if (nk > 1) BG_ISSUE(1, 1);
    if (nk > 2) BG_ISSUE(2, 2);

    for (int kt = 0; kt < nk; kt++) {
        if (kt + 2 < nk)      asm volatile("cp.async.wait_group 2;" ::: "memory");
        else if (kt + 1 < nk) asm volatile("cp.async.wait_group 1;" ::: "memory");
        else                  asm volatile("cp.async.wait_group 0;" ::: "memory");
        __syncthreads();
        if (kt + 3 < nk) BG_ISSUE(kt + 3, (kt + 3) & 3);

        const unsigned abase = asb + (unsigned)(((kt & 3) * 128 * PKH) << 1);
        const unsigned bbase = bsb + (unsigned)(((kt & 3) * 128 * PKH) << 1);

#pragma unroll
        for (int kk = 0; kk < 32; kk += 16) {
            unsigned a[4][4], b[4][2];
#pragma unroll
            for (int mi = 0; mi < 4; mi++) {
                const unsigned ad = abase +
                    (((wm * 64 + mi * 16 + (lane & 15)) * PKH + kk + (lane >> 4) * 8) << 1);
                asm volatile("ldmatrix.sync.aligned.m8n8.x4.shared.b16 {%0,%1,%2,%3}, [%4];"
                    : "=r"(a[mi][0]), "=r"(a[mi][1]), "=r"(a[mi][2]), "=r"(a[mi][3]) : "r"(ad));
            }
#pragma unroll
            for (int nj = 0; nj < 2; nj++) {
                const int g = lane >> 3, rr = lane & 7;
                const unsigned bd = bbase +
                    (((wn * 32 + nj * 16 + (g >> 1) * 8 + rr) * PKH + kk + (g & 1) * 8) << 1);
                asm volatile("ldmatrix.sync.aligned.m8n8.x4.shared.b16 {%0,%1,%2,%3}, [%4];"
                    : "=r"(b[nj * 2][0]), "=r"(b[nj * 2][1]),
                      "=r"(b[nj * 2 + 1][0]), "=r"(b[nj * 2 + 1][1]) : "r"(bd));
            }
#pragma unroll
            for (int mi = 0; mi < 4; mi++)
#pragma unroll
                for (int ni = 0; ni < 4; ni++)
                    asm volatile(
                        "mma.sync.aligned.m16n8k16.row.col.f32.bf16.bf16.f32 "
                        "{%0,%1,%2,%3}, {%4,%5,%6,%7}, {%8,%9}, {%0,%1,%2,%3};"
                        : "+f"(c[mi][ni][0]), "+f"(c[mi][ni][1]),
                          "+f"(c[mi][ni][2]), "+f"(c[mi][ni][3])
                        : "r"(a[mi][0]), "r"(a[mi][1]), "r"(a[mi][2]), "r"(a[mi][3]),
                          "r"(b[ni][0]), "r"(b[ni][1]));
        }
    }

#pragma unroll
    for (int mi = 0; mi < 4; mi++) {
        const int row = m0 + wm * 64 + mi * 16 + (lane >> 2);
#pragma unroll
        for (int ni = 0; ni < 4; ni++) {
            const int col = n0 + wn * 32 + ni * 8 + (lane & 3) * 2;
            const float bx = bias[col], by = bias[col + 1];
            float2 v0 = make_float2(c[mi][ni][0] + bx, c[mi][ni][1] + by);
            float2 v1 = make_float2(c[mi][ni][2] + bx, c[mi][ni][3] + by);
            *reinterpret_cast<float2*>(&C[(size_t)row * N + col]) = v0;
            *reinterpret_cast<float2*>(&C[(size_t)(row + 8) * N + col]) = v1;
        }
    }
}

__device__ __forceinline__ float fast_sig(float x) {
    return __fdividef(1.f, 1.f + __expf(-x));
}
__device__ __forceinline__ float fast_tanh(float x) {
    return 1.f - __fdividef(2.f, __expf(2.f * x) + 1.f);
}

// ---------------- tensor-core persistent BiGRU recurrence ----------------
// 128 CTAs: dir = cta>>6, ks = (cta&63)>>1 (16 k-cols), bg = cta&1 (32 batches).
// Arrive/wait split barrier (known-good round-7 sync structure).
// Whi fragments fully register-cached; Wlo fragments cached for iters 0..7.
// Epilogue concentrated on kh0 warps (kh1 parks at barrier) — round-12 showed
// spreading the tail across all warps lengthens the serial chain.
#define PA 1032   // A smem pitch (halves)
#define PW 520    // W smem pitch (halves)
__global__ void __launch_bounds__(256, 1) recur_tc_kernel(
    const float* __restrict__ xp,    // [dir][B*T, 1536] (includes b_ih)
    const float* __restrict__ w_hh,  // [2][1536][512]
    const float* __restrict__ b_hh,  // [2][1536]
    __nv_bfloat16* __restrict__ a3,  // layer-1 split A out [M, 3*1024] or nullptr
    int do_pool)
{
    extern __shared__ char smraw[];
    __nv_bfloat16* sWhi = reinterpret_cast<__nv_bfloat16*>(smraw);   // [48][PW]
    __nv_bfloat16* sWlo = sWhi + 48 * PW;                             // [48][PW]
    __nv_bfloat16* sA   = sWlo + 48 * PW;                             // [32][PA]
    float* sred  = reinterpret_cast<float*>(sA + 32 * PA);            // [128][13]

    const int cta = blockIdx.x;
    const int dir = cta >> 6;
    const int ks  = (cta & 63) >> 1;
    const int bg  = cta & 1;
    const int k0  = ks * 16;
    const int tid = threadIdx.x;
    const int warp = tid >> 5, lane = tid & 31;
    const int kh = warp >> 2;
    const int wm = (warp >> 1) & 1;
    const int wn = warp & 1;
    unsigned* bar = &g_bar4[dir * 2 + bg];

    // ---- load + split W_hh slice, rows ordered [blk(2)][gate(3)][kcl(8)]
    {
        const float* wsrc = w_hh + (size_t)dir * GG * HH;
        for (int idx = tid; idx < 48 * 128; idx += 256) {
            const int jj = idx >> 7;
            const int q  = (idx & 127) * 4;
            const int blk = jj / 24, within = jj % 24;
            const int gate = within >> 3, kcl = within & 7;
            const int grow = gate * HH + k0 + blk * 8 + kcl;
            const float4 v = *reinterpret_cast<const float4*>(&wsrc[(size_t)grow * HH + q]);
            const __nv_bfloat16 h0 = __float2bfloat16(v.x), h1 = __float2bfloat16(v.y);
            const __nv_bfloat16 h2 = __float2bfloat16(v.z), h3 = __float2bfloat16(v.w);
            const __nv_bfloat16 l0 = __float2bfloat16(v.x - __bfloat162float(h0));
            const __nv_bfloat16 l1 = __float2bfloat16(v.y - __bfloat162float(h1));
            const __nv_bfloat16 l2 = __float2bfloat16(v.z - __bfloat162float(h2));
            const __nv_bfloat16 l3 = __float2bfloat16(v.w - __bfloat162float(h3));
            __nv_bfloat162* dh = reinterpret_cast<__nv_bfloat162*>(sWhi + jj * PW + q);
            __nv_bfloat162* dl = reinterpret_cast<__nv_bfloat162*>(sWlo + jj * PW + q);
            dh[0] = __halves2bfloat162(h0, h1); dh[1] = __halves2bfloat162(h2, h3);
            dl[0] = __halves2bfloat162(l0, l1); dl[1] = __halves2bfloat162(l2, l3);
        }
    }

    const int r0  = wm * 16 + (lane >> 2);
    const int kc2 = wn * 8 + (lane & 3) * 2;
    float br0 = 0.f, br1 = 0.f, bz0 = 0.f, bz1 = 0.f, bn0 = 0.f, bn1 = 0.f;
    if (kh == 0) {
        br0 = b_hh[dir * GG + 0 * HH + k0 + kc2]; br1 = b_hh[dir * GG + 0 * HH + k0 + kc2 + 1];
        bz0 = b_hh[dir * GG + 1 * HH + k0 + kc2]; bz1 = b_hh[dir * GG + 1 * HH + k0 + kc2 + 1];
        bn0 = b_hh[dir * GG + 2 * HH + k0 + kc2]; bn1 = b_hh[dir * GG + 2 * HH + k0 + kc2 + 1];
    }
    float hprev[4] = {0.f, 0.f, 0.f, 0.f};
    float mx[4] = {-1e30f, -1e30f, -1e30f, -1e30f};
    unsigned bar_tgt = 0;
    __syncthreads();

    const unsigned sAb  = (unsigned)__cvta_generic_to_shared(sA);
    const unsigned sWhb = (unsigned)__cvta_generic_to_shared(sWhi);
    const unsigned sWlb = (unsigned)__cvta_generic_to_shared(sWlo);
    const int t128 = tid & 127;

    // ---- preload loop-invariant W fragments: Whi (all 16 iters), Wlo (iters 0..7)
    unsigned wf[16][6];
    unsigned wl[8][6];
    {
        const int g_ = lane >> 3, rr_ = lane & 7;
#pragma unroll
        for (int i = 0; i < 16; i++) {
            const int kk = kh * 256 + i * 16;
            const unsigned bo  = (unsigned)(((wn * 24 + (g_ >> 1) * 8 + rr_) * PW + kk + (g_ & 1) * 8) << 1);
            const unsigned bo2 = (unsigned)(((wn * 24 + 16 + rr_) * PW + kk + ((lane >> 3) & 1) * 8) << 1);
            asm volatile("ldmatrix.sync.aligned.m8n8.x4.shared.b16 {%0,%1,%2,%3}, [%4];"
                : "=r"(wf[i][0]), "=r"(wf[i][1]), "=r"(wf[i][2]), "=r"(wf[i][3]) : "r"(sWhb + bo));
            asm volatile("ldmatrix.sync.aligned.m8n8.x2.shared.b16 {%0,%1}, [%2];"
                : "=r"(wf[i][4]), "=r"(wf[i][5]) : "r"(sWhb + bo2));
            if (i < 8) {
                asm volatile("ldmatrix.sync.aligned.m8n8.x4.shared.b16 {%0,%1,%2,%3}, [%4];"
                    : "=r"(wl[i][0]), "=r"(wl[i][1]), "=r"(wl[i][2]), "=r"(wl[i][3]) : "r"(sWlb + bo));
                asm volatile("ldmatrix.sync.aligned.m8n8.x2.shared.b16 {%0,%1}, [%2];"
                    : "=r"(wl[i][4]), "=r"(wl[i][5]) : "r"(sWlb + bo2));
            }
        }
    }

    for (int s = 0; s < TT; s++) {
        const int t = dir ? (TT - 1 - s) : s;
        const int p = s & 1;

        // ---- spin-window work: prefetch xp epilogue operands (kh==0 only)
        float2 xr0, xr1, xz0, xz1, xn0, xn1;
        if (kh == 0) {
            const size_t xb0 = ((size_t)(dir * BB + bg * 32 + r0) * TT + t) * GG + k0 + kc2;
            const size_t xb1 = ((size_t)(dir * BB + bg * 32 + r0 + 8) * TT + t) * GG + k0 + kc2;
            xr0 = __ldg(reinterpret_cast<const float2*>(xp + xb0));
            xz0 = __ldg(reinterpret_cast<const float2*>(xp + xb0 + HH));
            xn0 = __ldg(reinterpret_cast<const float2*>(xp + xb0 + 2 * HH));
            xr1 = __ldg(reinterpret_cast<const float2*>(xp + xb1));
            xz1 = __ldg(reinterpret_cast<const float2*>(xp + xb1 + HH));
            xn1 = __ldg(reinterpret_cast<const float2*>(xp + xb1 + 2 * HH));
        }

        // ---- wait for step-s h (counter >= 32*s)
        if (tid == 0 && s > 0) {
            unsigned v;
            do {
                asm volatile("ld.acquire.gpu.global.u32 %0, [%1];"
                             : "=r"(v) : "l"(bar) : "memory");
            } while (v < bar_tgt);
        }
        __syncthreads();

        // ---- issue own-group h chunks: hi (cols kh*256), then lo (512+kh*256)
        {
            const __nv_bfloat16* hsrc = &g_hA[p][dir][bg * 32][0];
#pragma unroll
            for (int it = 0; it < 8; it++) {
                const int idx = it * 128 + t128;
                const int row = idx >> 5, seg = idx & 31;
                const int col = kh * 256 + seg * 8;
                asm volatile("cp.async.cg.shared.global [%0], [%1], 16;"
                    :: "r"(sAb + (unsigned)((row * PA + col) << 1)),
                       "l"(hsrc + row * 1024 + col) : "memory");
            }
            asm volatile("cp.async.commit_group;" ::: "memory");
#pragma unroll
            for (int it = 0; it < 8; it++) {
                const int idx = it * 128 + t128;
                const int row = idx >> 5, seg = idx & 31;
                const int col = 512 + kh * 256 + seg * 8;
                asm volatile("cp.async.cg.shared.global [%0], [%1], 16;"
                    :: "r"(sAb + (unsigned)((row * PA + col) << 1)),
                       "l"(hsrc + row * 1024 + col) : "memory");
            }
            asm volatile("cp.async.commit_group;" ::: "memory");
        }

        float c0[4] = {0.f, 0.f, 0.f, 0.f};
        float c1[4] = {0.f, 0.f, 0.f, 0.f};
        float c2[4] = {0.f, 0.f, 0.f, 0.f};

        // ---- phase A: hi chunk ready -> a_hi x (Whi[regs], Wlo[regs 0..7 / smem 8..15])
        asm volatile("cp.async.wait_group 1;" ::: "memory");
        asm volatile("bar.sync %0, 128;" :: "r"(1 + kh) : "memory");
#pragma unroll
        for (int i = 0; i < 16; i++) {
            const int kk = kh * 256 + i * 16;
            unsigned a0, a1, a2, a3r;
            const unsigned ad = sAb + ((((wm * 16 + (lane & 15)) * PA) + kk + (lane >> 4) * 8) << 1);
            asm volatile("ldmatrix.sync.aligned.m8n8.x4.shared.b16 {%0,%1,%2,%3}, [%4];"
                : "=r"(a0), "=r"(a1), "=r"(a2), "=r"(a3r) : "r"(ad));
#define MMA1(CC, B0, B1) \
            asm volatile("mma.sync.aligned.m16n8k16.row.col.f32.bf16.bf16.f32 " \
                "{%0,%1,%2,%3}, {%4,%5,%6,%7}, {%8,%9}, {%0,%1,%2,%3};" \
                : "+f"(CC[0]), "+f"(CC[1]), "+f"(CC[2]), "+f"(CC[3]) \
                : "r"(a0), "r"(a1), "r"(a2), "r"(a3r), "r"(B0), "r"(B1))
            MMA1(c0, wf[i][0], wf[i][1]); MMA1(c1, wf[i][2], wf[i][3]); MMA1(c2, wf[i][4], wf[i][5]);
            if (i < 8) {
                MMA1(c0, wl[i][0], wl[i][1]); MMA1(c1, wl[i][2], wl[i][3]); MMA1(c2, wl[i][4], wl[i][5]);
            } else {
                unsigned l00, l01, l10, l11, l20, l21;
                const int g_ = lane >> 3, rr_ = lane & 7;
                const unsigned bo  = (unsigned)(((wn * 24 + (g_ >> 1) * 8 + rr_) * PW + kk + (g_ & 1) * 8) << 1);
                const unsigned bo2 = (unsigned)(((wn * 24 + 16 + rr_) * PW + kk + ((lane >> 3) & 1) * 8) << 1);
                asm volatile("ldmatrix.sync.aligned.m8n8.x4.shared.b16 {%0,%1,%2,%3}, [%4];"
                    : "=r"(l00), "=r"(l01), "=r"(l10), "=r"(l11) : "r"(sWlb + bo));
                asm volatile("ldmatrix.sync.aligned.m8n8.x2.shared.b16 {%0,%1}, [%2];"
                    : "=r"(l20), "=r"(l21) : "r"(sWlb + bo2));
                MMA1(c0, l00, l01); MMA1(c1, l10, l11); MMA1(c2, l20, l21);
            }
        }

        // ---- phase B: lo chunk ready -> a_lo x Whi[regs]
        asm volatile("cp.async.wait_group 0;" ::: "memory");
        asm volatile("bar.sync %0, 128;" :: "r"(1 + kh) : "memory");
#pragma unroll
        for (int i = 0; i < 16; i++) {
            const int kk = kh * 256 + i * 16;
            unsigned a0, a1, a2, a3r;
            const unsigned ad = sAb + ((((wm * 16 + (lane & 15)) * PA) + 512 + kk + (lane >> 4) * 8) << 1);
            asm volatile("ldmatrix.sync.aligned.m8n8.x4.shared.b16 {%0,%1,%2,%3}, [%4];"
                : "=r"(a0), "=r"(a1), "=r"(a2), "=r"(a3r) : "r"(ad));
            MMA1(c0, wf[i][0], wf[i][1]); MMA1(c1, wf[i][2], wf[i][3]); MMA1(c2, wf[i][4], wf[i][5]);
        }

        // ---- reduce k-halves
        if (kh == 1) {
            float* rp = sred + (size_t)(((warp - 4) << 5) + lane) * 13;
#pragma unroll
            for (int q = 0; q < 4; q++) {
                rp[q] = c0[q]; rp[4 + q] = c1[q]; rp[8 + q] = c2[q];
            }
        }
        __syncthreads();

        float hv[4];
        __nv_bfloat162 hp2[2], lp2[2];
        if (kh == 0) {
            const float* rp = sred + (size_t)((warp << 5) + lane) * 13;
#pragma unroll
            for (int q = 0; q < 4; q++) {
                const float gr = c0[q] + rp[q]     + ((q & 1) ? br1 : br0);
                const float gz = c1[q] + rp[4 + q] + ((q & 1) ? bz1 : bz0);
                const float gn = c2[q] + rp[8 + q] + ((q & 1) ? bn1 : bn0);
                const float2 xr = (q >> 1) ? xr1 : xr0;
                const float2 xz = (q >> 1) ? xz1 : xz0;
                const float2 xn = (q >> 1) ? xn1 : xn0;
                const float rg = fast_sig(((q & 1) ? xr.y : xr.x) + gr);
                const float zg = fast_sig(((q & 1) ? xz.y : xz.x) + gz);
                const float ng = fast_tanh(((q & 1) ? xn.y : xn.x) + rg * gn);
                hv[q] = (1.f - zg) * ng + zg * hprev[q];
                hprev[q] = hv[q];
            }
            // split h, store both rows to next buffer (these must precede arrive)
#pragma unroll
            for (int rsel = 0; rsel < 2; rsel++) {
                const float v0 = hv[rsel * 2], v1 = hv[rsel * 2 + 1];
                const __nv_bfloat16 h0 = __float2bfloat16(v0);
                const __nv_bfloat16 h1 = __float2bfloat16(v1);
                const __nv_bfloat16 l0 = __float2bfloat16(v0 - __bfloat162float(h0));
                const __nv_bfloat16 l1 = __float2bfloat16(v1 - __bfloat162float(h1));
                hp2[rsel] = __halves2bfloat162(h0, h1);
                lp2[rsel] = __halves2bfloat162(l0, l1);
                const int brow = bg * 32 + r0 + rsel * 8;
                __nv_bfloat16* dst = &g_hA[1 - p][dir][brow][k0 + kc2];
                __stcg(reinterpret_cast<unsigned*>(dst),
                       *reinterpret_cast<const unsigned*>(&hp2[rsel]));
                __stcg(reinterpret_cast<unsigned*>(dst + 512),
                       *reinterpret_cast<const unsigned*>(&lp2[rsel]));
            }
        }
        __syncthreads();
        // ---- arrive (release h stores), then do deferred output work in spin window
        if (tid == 0) {
            bar_tgt += 32u;
            unsigned prev;
            asm volatile("atom.acq_rel.gpu.global.add.u32 %0, [%1], 1;"
                         : "=r"(prev) : "l"(bar) : "memory");
            (void)prev;
        } else {
            bar_tgt += 32u;
        }
        if (kh == 0) {
            if (do_pool) {
#pragma unroll
                for (int q = 0; q < 4; q++) mx[q] = fmaxf(mx[q], hv[q]);
            }
            if (a3) {
#pragma unroll
                for (int rsel = 0; rsel < 2; rsel++) {
                    const int brow = bg * 32 + r0 + rsel * 8;
                    __nv_bfloat16* ad3 = a3 + ((size_t)brow * TT + t) * 3072 + dir * HH + k0 + kc2;
                    *reinterpret_cast<unsigned*>(ad3)        = *reinterpret_cast<const unsigned*>(&hp2[rsel]);
                    *reinterpret_cast<unsigned*>(ad3 + 1024) = *reinterpret_cast<const unsigned*>(&hp2[rsel]);
                    *reinterpret_cast<unsigned*>(ad3 + 2048) = *reinterpret_cast<const unsigned*>(&lp2[rsel]);
                }
            }
        }
    }

    if (do_pool && kh == 0) {
#pragma unroll
        for (int q = 0; q < 4; q++) {
            const int brow = bg * 32 + r0 + (q >> 1) * 8;
            g_pooled[(size_t)brow * (2 * HH) + dir * HH + k0 + kc2 + (q & 1)] = mx[q];
        }
    }
}

// ---------------- classifier head ----------------
__global__ void mlp1_kernel(const float* __restrict__ w1, const float* __restrict__ b1) {
    const int warp = (blockIdx.x * blockDim.x + threadIdx.x) >> 5;
    const int lane = threadIdx.x & 31;
    if (warp >= BB * 128) return;
    const int b = warp >> 7, j = warp & 127;
    const float* p = g_pooled + (size_t)b * 2 * HH;
    const float* w = w1 + (size_t)j * 2 * HH;
    float s = 0.f;
    for (int k = lane; k < 2 * HH; k += 32) s = fmaf(p[k], w[k], s);
#pragma unroll
    for (int o = 16; o; o >>= 1) s += __shfl_xor_sync(0xffffffffu, s, o);
    if (lane == 0) g_hid[b * 128 + j] = fmaxf(s + b1[j], 0.f);
}

__global__ void mlp2_kernel(const float* __restrict__ w2, const float* __restrict__ b2,
                            float* __restrict__ out) {
    const int t = threadIdx.x;
    if (t < BB * 2) {
        const int b = t >> 1, c = t & 1;
        float s = b2[c];
        const float* h = g_hid + b * 128;
        const float* w = w2 + c * 128;
        for (int k = 0; k < 128; k++) s = fmaf(h[k], w[k], s);
        out[t] = s;
    }
}

// ---------------- launch ----------------
extern "C" void kernel_launch(void* const* d_in, const int* in_sizes, int n_in,
                              void* d_out, int out_size) {
    const int*   x    = (const int*)d_in[0];
    const float* emb  = (const float*)d_in[1];
    const float* wih0 = (const float*)d_in[2];
    const float* whh0 = (const float*)d_in[3];
    const float* bih0 = (const float*)d_in[4];
    const float* bhh0 = (const float*)d_in[5];
    const float* wih1 = (const float*)d_in[6];
    const float* whh1 = (const float*)d_in[7];
    const float* bih1 = (const float*)d_in[8];
    const float* bhh1 = (const float*)d_in[9];
    const float* w1   = (const float*)d_in[10];
    const float* b1   = (const float*)d_in[11];
    const float* w2   = (const float*)d_in[12];
    const float* b2   = (const float*)d_in[13];

    float* xp_p = nullptr;
    __nv_bfloat16 *a3_p = nullptr, *w3_p = nullptr;
    cudaGetSymbolAddress((void**)&xp_p, g_xp);
    cudaGetSymbolAddress((void**)&a3_p, g_a3);
    cudaGetSymbolAddress((void**)&w3_p, g_w3);

    const size_t sm_tc = (size_t)(2 * 48 * PW + 32 * PA) * sizeof(__nv_bfloat16)
                       + (size_t)(128 * 13) * sizeof(float);
    cudaFuncSetAttribute(recur_tc_kernel, cudaFuncAttributeMaxDynamicSharedMemorySize, (int)sm_tc);
    const size_t sm_gemm = (size_t)8 * 128 * PKH * sizeof(__nv_bfloat16);
    cudaFuncSetAttribute(bgemm_kernel, cudaFuncAttributeMaxDynamicSharedMemorySize, (int)sm_gemm);

    // ---- layer 0 ----
    init_kernel<<<64, 256>>>();
    embed_split_kernel<<<MM, 160>>>(x, emb);
    {
        const long pw = (long)(2 * GG) * (320 / 2);
        conv_split_kernel<<<(unsigned)((pw + 255) / 256), 256>>>(wih0, w3_p, 2 * GG, EE, 320, 1);
    }
    bgemm_kernel<<<dim3(GG / 128, MM / 128, 2), 256, sm_gemm>>>(a3_p, w3_p, bih0, xp_p, MM, GG, 960);
    // W split for layer 1
    {
        const long pw = (long)(2 * GG) * (1024 / 2);
        conv_split_kernel<<<(unsigned)((pw + 255) / 256), 256>>>(wih1, w3_p, 2 * GG, 2 * HH, 1024, 1);
    }
    recur_tc_kernel<<<128, 256, sm_tc>>>(xp_p, whh0, bhh0, a3_p, 0);  // writes layer-1 split A

    // ---- layer 1 ----
    bgemm_kernel<<<dim3(GG / 128, MM / 128, 2), 256, sm_gemm>>>(a3_p, w3_p, bih1, xp_p, MM, GG, 3072);
    init_kernel<<<64, 256>>>();
    recur_tc_kernel<<<128, 256, sm_tc>>>(xp_p, whh1, bhh1, nullptr, 1);

    // ---- head ----
    mlp1_kernel<<<(BB * 128 * 32) / 256, 256>>>(w1, b1);
    mlp2_kernel<<<1, 128>>>(w2, b2, (float*)d_out);
}

// round 16
// speedup vs baseline: 1.1172x; 1.0110x over previous
#include <cuda_runtime.h>
#include <cuda_bf16.h>
#include <math.h>
#include <stdint.h>

#define BB 64
#define TT 256
#define EE 300
#define HH 512
#define GG 1536               // 3*H
#define MM (BB*TT)            // 16384

// ---------------- scratch (static device allocations only) ----------------
__device__ __align__(256) float g_xp[2 * MM * GG];       // input projections [dir][B*T, 1536]
__device__ __align__(256) __nv_bfloat16 g_hA[2][2][BB][1024]; // h split [buf][dir][b][hi|lo]
__device__ __align__(256) float g_pooled[BB * 2 * HH];   // maxpool [B, 1024]
__device__ __align__(256) float g_hid[BB * 128];         // mlp hidden
__device__ __align__(256) __nv_bfloat16 g_a3[MM * 2 * 1024];        // split A [M, hi|lo]
__device__ __align__(256) __nv_bfloat16 g_w3[2 * GG * 2 * 1024];    // split W [2N, hi|lo]
__device__ unsigned g_bar4[4];

// ---------------- init ----------------
__global__ void init_kernel() {
    const int n = 2 * 2 * BB * 1024 / 2;
    unsigned* p = reinterpret_cast<unsigned*>(&g_hA[0][0][0][0]);
    for (int i = blockIdx.x * blockDim.x + threadIdx.x; i < n; i += gridDim.x * blockDim.x)
        p[i] = 0u;
    if (blockIdx.x == 0 && threadIdx.x < 4) g_bar4[threadIdx.x] = 0u;
}

// ---------------- fused embedding gather + bf16 split (A slabs [hi|lo], Kp=320) ----------------
__global__ void embed_split_kernel(const int* __restrict__ x, const float* __restrict__ emb) {
    const int tok = blockIdx.x;
    const int row = x[tok];
    const int pi = threadIdx.x;          // pair index 0..159
    const int k0 = pi * 2;
    const float v0 = (k0     < EE) ? emb[(size_t)row * EE + k0]     : 0.f;
    const float v1 = (k0 + 1 < EE) ? emb[(size_t)row * EE + k0 + 1] : 0.f;
    const __nv_bfloat16 h0 = __float2bfloat16(v0), h1 = __float2bfloat16(v1);
    const __nv_bfloat16 l0 = __float2bfloat16(v0 - __bfloat162float(h0));
    const __nv_bfloat16 l1 = __float2bfloat16(v1 - __bfloat162float(h1));
    const __nv_bfloat162 hh = __halves2bfloat162(h0, h1);
    const __nv_bfloat162 ll = __halves2bfloat162(l0, l1);
    __nv_bfloat162* d = reinterpret_cast<__nv_bfloat162*>(g_a3 + (size_t)tok * 640);
    d[pi] = hh; d[pi + 160] = ll;
}

// ---------------- bf16 split conversion (weights): slabs [hi | lo] ----------------
__global__ void conv_split_kernel(const float* __restrict__ src, __nv_bfloat16* __restrict__ dst,
                                  int rows, int Ksrc, int Kp) {
    const long i = (long)blockIdx.x * blockDim.x + threadIdx.x;
    const long total = (long)rows * (Kp / 2);
    if (i >= total) return;
    const int m  = (int)(i / (Kp / 2));
    const int k0 = (int)(i % (Kp / 2)) * 2;
    const float v0 = (k0     < Ksrc) ? src[(size_t)m * Ksrc + k0]     : 0.f;
    const float v1 = (k0 + 1 < Ksrc) ? src[(size_t)m * Ksrc + k0 + 1] : 0.f;
    const __nv_bfloat16 h0 = __float2bfloat16(v0), h1 = __float2bfloat16(v1);
    const __nv_bfloat16 l0 = __float2bfloat16(v0 - __bfloat162float(h0));
    const __nv_bfloat16 l1 = __float2bfloat16(v1 - __bfloat162float(h1));
    const __nv_bfloat162 hh = __halves2bfloat162(h0, h1);
    const __nv_bfloat162 ll = __halves2bfloat162(l0, l1);
    __nv_bfloat162* d = reinterpret_cast<__nv_bfloat162*>(dst + (size_t)m * 2 * Kp);
    const int p = k0 >> 1, s = Kp >> 1;
    d[p] = hh; d[p + s] = ll;
}

// ---------------- bf16 tensor-core GEMM, 4-stage cp.async pipeline ----------------
// 3-pass split GEMM over [hi|lo] slabs: pass0 Ahi*Whi, pass1 Ahi*Wlo, pass2 Alo*Whi.
// Same summation order as the old [hi|hi|lo]x[hi|lo|hi] concatenation.
#define PKH 40
__global__ void __launch_bounds__(256, 2) bgemm_kernel(
    const __nv_bfloat16* __restrict__ A,   // [M, 2*Kp]
    const __nv_bfloat16* __restrict__ W,   // [2N, 2*Kp]
    const float* __restrict__ bias, float* __restrict__ C,
    int M, int N, int Kp)
{
    extern __shared__ __nv_bfloat16 gsm[];
    __nv_bfloat16* As = gsm;                    // [4][128*PKH]
    __nv_bfloat16* Bs = gsm + 4 * 128 * PKH;    // [4][128*PKH]

    const int z = blockIdx.z;
    const int K2 = 2 * Kp;
    W    += (size_t)z * N * K2;
    bias += (size_t)z * N;
    C    += (size_t)z * M * N;

    const int m0 = blockIdx.y * 128, n0 = blockIdx.x * 128;
    const int tid = threadIdx.x;
    const int warp = tid >> 5, lane = tid & 31;
    const int wm = warp >> 2, wn = warp & 3;

    float c[4][4][4];
#pragma unroll
    for (int mi = 0; mi < 4; mi++)
#pragma unroll
        for (int ni = 0; ni < 4; ni++)
#pragma unroll
            for (int q = 0; q < 4; q++) c[mi][ni][q] = 0.f;

    const int lrow = tid >> 2;
    const int lcol = (tid & 3) * 8;
    const unsigned asb = (unsigned)__cvta_generic_to_shared(As);
    const unsigned bsb = (unsigned)__cvta_generic_to_shared(Bs);
    const int nkp = Kp / 32;
    const int nk = 3 * nkp;

#define BG_ISSUE(KT, BUF) do {                                                        \
        const int pass_ = (KT) / nkp;                                                 \
        const int ktp_  = (KT) - pass_ * nkp;                                         \
        const int ao_k  = ((pass_ == 2) ? Kp : 0) + ktp_ * 32 + lcol;                 \
        const int wo_k  = ((pass_ == 1) ? Kp : 0) + ktp_ * 32 + lcol;                 \
        const size_t ar_ = (size_t)(m0 + lrow) * K2 + ao_k;                           \
        const size_t br_ = (size_t)(n0 + lrow) * K2 + wo_k;                           \
        const unsigned ao_ = (unsigned)((((BUF) * 128 + lrow) * PKH + lcol) << 1);    \
        asm volatile("cp.async.cg.shared.global [%0],[%1],16;"                        \
            :: "r"(asb + ao_), "l"(A + ar_) : "memory");                              \
        asm volatile("cp.async.cg.shared.global [%0],[%1],16;"                        \
            :: "r"(asb + ao_ + (unsigned)((64 * PKH) << 1)), "l"(A + ar_ + (size_t)64 * K2) : "memory"); \
        asm volatile("cp.async.cg.shared.global [%0],[%1],16;"                        \
            :: "r"(bsb + ao_), "l"(W + br_) : "memory");                              \
        asm volatile("cp.async.cg.shared.global [%0],[%1],16;"                        \
            :: "r"(bsb + ao_ + (unsigned)((64 * PKH) << 1)), "l"(W + br_ + (size_t)64 * K2) : "memory"); \
        asm volatile("cp.async.commit_group;" ::: "memory");                          \
    } while (0)

    BG_ISSUE(0, 0);
    if (nk > 1) BG_ISSUE(1, 1);
    if (nk > 2) BG_ISSUE(2, 2);

    for (int kt = 0; kt < nk; kt++) {
        if (kt + 2 < nk)      asm volatile("cp.async.wait_group 2;" ::: "memory");
        else if (kt + 1 < nk) asm volatile("cp.async.wait_group 1;" ::: "memory");
        else                  asm volatile("cp.async.wait_group 0;" ::: "memory");
        __syncthreads();
        if (kt + 3 < nk) BG_ISSUE(kt + 3, (kt + 3) & 3);

        const unsigned abase = asb + (unsigned)(((kt & 3) * 128 * PKH) << 1);
        const unsigned bbase = bsb + (unsigned)(((kt & 3) * 128 * PKH) << 1);

#pragma unroll
        for (int kk = 0; kk < 32; kk += 16) {
            unsigned a[4][4], b[4][2];
#pragma unroll
            for (int mi = 0; mi < 4; mi++) {
                const unsigned ad = abase +
                    (((wm * 64 + mi * 16 + (lane & 15)) * PKH + kk + (lane >> 4) * 8) << 1);
                asm volatile("ldmatrix.sync.aligned.m8n8.x4.shared.b16 {%0,%1,%2,%3}, [%4];"
                    : "=r"(a[mi][0]), "=r"(a[mi][1]), "=r"(a[mi][2]), "=r"(a[mi][3]) : "r"(ad));
            }
#pragma unroll
            for (int nj = 0; nj < 2; nj++) {
                const int g = lane >> 3, rr = lane & 7;
                const unsigned bd = bbase +
                    (((wn * 32 + nj * 16 + (g >> 1) * 8 + rr) * PKH + kk + (g & 1) * 8) << 1);
                asm volatile("ldmatrix.sync.aligned.m8n8.x4.shared.b16 {%0,%1,%2,%3}, [%4];"
                    : "=r"(b[nj * 2][0]), "=r"(b[nj * 2][1]),
                      "=r"(b[nj * 2 + 1][0]), "=r"(b[nj * 2 + 1][1]) : "r"(bd));
            }
#pragma unroll
            for (int mi = 0; mi < 4; mi++)
#pragma unroll
                for (int ni = 0; ni < 4; ni++)
                    asm volatile(
                        "mma.sync.aligned.m16n8k16.row.col.f32.bf16.bf16.f32 "
                        "{%0,%1,%2,%3}, {%4,%5,%6,%7}, {%8,%9}, {%0,%1,%2,%3};"
                        : "+f"(c[mi][ni][0]), "+f"(c[mi][ni][1]),
                          "+f"(c[mi][ni][2]), "+f"(c[mi][ni][3])
                        : "r"(a[mi][0]), "r"(a[mi][1]), "r"(a[mi][2]), "r"(a[mi][3]),
                          "r"(b[ni][0]), "r"(b[ni][1]));
        }
    }

#pragma unroll
    for (int mi = 0; mi < 4; mi++) {
        const int row = m0 + wm * 64 + mi * 16 + (lane >> 2);
#pragma unroll
        for (int ni = 0; ni < 4; ni++) {
            const int col = n0 + wn * 32 + ni * 8 + (lane & 3) * 2;
            const float bx = bias[col], by = bias[col + 1];
            float2 v0 = make_float2(c[mi][ni][0] + bx, c[mi][ni][1] + by);
            float2 v1 = make_float2(c[mi][ni][2] + bx, c[mi][ni][3] + by);
            *reinterpret_cast<float2*>(&C[(size_t)row * N + col]) = v0;
            *reinterpret_cast<float2*>(&C[(size_t)(row + 8) * N + col]) = v1;
        }
    }
}

__device__ __forceinline__ float fast_sig(float x) {
    return __fdividef(1.f, 1.f + __expf(-x));
}
__device__ __forceinline__ float fast_tanh(float x) {
    return 1.f - __fdividef(2.f, __expf(2.f * x) + 1.f);
}

// ---------------- tensor-core persistent BiGRU recurrence ----------------
// (round-11 best config; a3 epilogue now writes [hi|lo], pitch 2048)
#define PA 1032   // A smem pitch (halves)
#define PW 520    // W smem pitch (halves)
__global__ void __launch_bounds__(256, 1) recur_tc_kernel(
    const float* __restrict__ xp,    // [dir][B*T, 1536] (includes b_ih)
    const float* __restrict__ w_hh,  // [2][1536][512]
    const float* __restrict__ b_hh,  // [2][1536]
    __nv_bfloat16* __restrict__ a3,  // layer-1 split A out [M, 2*1024] or nullptr
    int do_pool)
{
    extern __shared__ char smraw[];
    __nv_bfloat16* sWhi = reinterpret_cast<__nv_bfloat16*>(smraw);   // [48][PW]
    __nv_bfloat16* sWlo = sWhi + 48 * PW;                             // [48][PW]
    __nv_bfloat16* sA   = sWlo + 48 * PW;                             // [32][PA]
    float* sred  = reinterpret_cast<float*>(sA + 32 * PA);            // [128][13]

    const int cta = blockIdx.x;
    const int dir = cta >> 6;
    const int ks  = (cta & 63) >> 1;
    const int bg  = cta & 1;
    const int k0  = ks * 16;
    const int tid = threadIdx.x;
    const int warp = tid >> 5, lane = tid & 31;
    const int kh = warp >> 2;
    const int wm = (warp >> 1) & 1;
    const int wn = warp & 1;
    unsigned* bar = &g_bar4[dir * 2 + bg];

    {
        const float* wsrc = w_hh + (size_t)dir * GG * HH;
        for (int idx = tid; idx < 48 * 128; idx += 256) {
            const int jj = idx >> 7;
            const int q  = (idx & 127) * 4;
            const int blk = jj / 24, within = jj % 24;
            const int gate = within >> 3, kcl = within & 7;
            const int grow = gate * HH + k0 + blk * 8 + kcl;
            const float4 v = *reinterpret_cast<const float4*>(&wsrc[(size_t)grow * HH + q]);
            const __nv_bfloat16 h0 = __float2bfloat16(v.x), h1 = __float2bfloat16(v.y);
            const __nv_bfloat16 h2 = __float2bfloat16(v.z), h3 = __float2bfloat16(v.w);
            const __nv_bfloat16 l0 = __float2bfloat16(v.x - __bfloat162float(h0));
            const __nv_bfloat16 l1 = __float2bfloat16(v.y - __bfloat162float(h1));
            const __nv_bfloat16 l2 = __float2bfloat16(v.z - __bfloat162float(h2));
            const __nv_bfloat16 l3 = __float2bfloat16(v.w - __bfloat162float(h3));
            __nv_bfloat162* dh = reinterpret_cast<__nv_bfloat162*>(sWhi + jj * PW + q);
            __nv_bfloat162* dl = reinterpret_cast<__nv_bfloat162*>(sWlo + jj * PW + q);
            dh[0] = __halves2bfloat162(h0, h1); dh[1] = __halves2bfloat162(h2, h3);
            dl[0] = __halves2bfloat162(l0, l1); dl[1] = __halves2bfloat162(l2, l3);
        }
    }

    const int r0  = wm * 16 + (lane >> 2);
    const int kc2 = wn * 8 + (lane & 3) * 2;
    float br0 = 0.f, br1 = 0.f, bz0 = 0.f, bz1 = 0.f, bn0 = 0.f, bn1 = 0.f;
    if (kh == 0) {
        br0 = b_hh[dir * GG + 0 * HH + k0 + kc2]; br1 = b_hh[dir * GG + 0 * HH + k0 + kc2 + 1];
        bz0 = b_hh[dir * GG + 1 * HH + k0 + kc2]; bz1 = b_hh[dir * GG + 1 * HH + k0 + kc2 + 1];
        bn0 = b_hh[dir * GG + 2 * HH + k0 + kc2]; bn1 = b_hh[dir * GG + 2 * HH + k0 + kc2 + 1];
    }
    float hprev[4] = {0.f, 0.f, 0.f, 0.f};
    float mx[4] = {-1e30f, -1e30f, -1e30f, -1e30f};
    unsigned bar_tgt = 0;
    __syncthreads();

    const unsigned sAb  = (unsigned)__cvta_generic_to_shared(sA);
    const unsigned sWhb = (unsigned)__cvta_generic_to_shared(sWhi);
    const unsigned sWlb = (unsigned)__cvta_generic_to_shared(sWlo);
    const int t128 = tid & 127;

    unsigned wf[16][6];
    unsigned wl[8][6];
    {
        const int g_ = lane >> 3, rr_ = lane & 7;
#pragma unroll
        for (int i = 0; i < 16; i++) {
            const int kk = kh * 256 + i * 16;
            const unsigned bo  = (unsigned)(((wn * 24 + (g_ >> 1) * 8 + rr_) * PW + kk + (g_ & 1) * 8) << 1);
            const unsigned bo2 = (unsigned)(((wn * 24 + 16 + rr_) * PW + kk + ((lane >> 3) & 1) * 8) << 1);
            asm volatile("ldmatrix.sync.aligned.m8n8.x4.shared.b16 {%0,%1,%2,%3}, [%4];"
                : "=r"(wf[i][0]), "=r"(wf[i][1]), "=r"(wf[i][2]), "=r"(wf[i][3]) : "r"(sWhb + bo));
            asm volatile("ldmatrix.sync.aligned.m8n8.x2.shared.b16 {%0,%1}, [%2];"
                : "=r"(wf[i][4]), "=r"(wf[i][5]) : "r"(sWhb + bo2));
            if (i < 8) {
                asm volatile("ldmatrix.sync.aligned.m8n8.x4.shared.b16 {%0,%1,%2,%3}, [%4];"
                    : "=r"(wl[i][0]), "=r"(wl[i][1]), "=r"(wl[i][2]), "=r"(wl[i][3]) : "r"(sWlb + bo));
                asm volatile("ldmatrix.sync.aligned.m8n8.x2.shared.b16 {%0,%1}, [%2];"
                    : "=r"(wl[i][4]), "=r"(wl[i][5]) : "r"(sWlb + bo2));
            }
        }
    }

    for (int s = 0; s < TT; s++) {
        const int t = dir ? (TT - 1 - s) : s;
        const int p = s & 1;

        float2 xr0, xr1, xz0, xz1, xn0, xn1;
        if (kh == 0) {
            const size_t xb0 = ((size_t)(dir * BB + bg * 32 + r0) * TT + t) * GG + k0 + kc2;
            const size_t xb1 = ((size_t)(dir * BB + bg * 32 + r0 + 8) * TT + t) * GG + k0 + kc2;
            xr0 = __ldg(reinterpret_cast<const float2*>(xp + xb0));
            xz0 = __ldg(reinterpret_cast<const float2*>(xp + xb0 + HH));
            xn0 = __ldg(reinterpret_cast<const float2*>(xp + xb0 + 2 * HH));
            xr1 = __ldg(reinterpret_cast<const float2*>(xp + xb1));
            xz1 = __ldg(reinterpret_cast<const float2*>(xp + xb1 + HH));
            xn1 = __ldg(reinterpret_cast<const float2*>(xp + xb1 + 2 * HH));
        }

        if (tid == 0 && s > 0) {
            unsigned v;
            do {
                asm volatile("ld.acquire.gpu.global.u32 %0, [%1];"
                             : "=r"(v) : "l"(bar) : "memory");
            } while (v < bar_tgt);
        }
        __syncthreads();

        {
            const __nv_bfloat16* hsrc = &g_hA[p][dir][bg * 32][0];
#pragma unroll
            for (int it = 0; it < 8; it++) {
                const int idx = it * 128 + t128;
                const int row = idx >> 5, seg = idx & 31;
                const int col = kh * 256 + seg * 8;
                asm volatile("cp.async.cg.shared.global [%0], [%1], 16;"
                    :: "r"(sAb + (unsigned)((row * PA + col) << 1)),
                       "l"(hsrc + row * 1024 + col) : "memory");
            }
            asm volatile("cp.async.commit_group;" ::: "memory");
#pragma unroll
            for (int it = 0; it < 8; it++) {
                const int idx = it * 128 + t128;
                const int row = idx >> 5, seg = idx & 31;
                const int col = 512 + kh * 256 + seg * 8;
                asm volatile("cp.async.cg.shared.global [%0], [%1], 16;"
                    :: "r"(sAb + (unsigned)((row * PA + col) << 1)),
                       "l"(hsrc + row * 1024 + col) : "memory");
            }
            asm volatile("cp.async.commit_group;" ::: "memory");
        }

        float c0[4] = {0.f, 0.f, 0.f, 0.f};
        float c1[4] = {0.f, 0.f, 0.f, 0.f};
        float c2[4] = {0.f, 0.f, 0.f, 0.f};

        asm volatile("cp.async.wait_group 1;" ::: "memory");
        asm volatile("bar.sync %0, 128;" :: "r"(1 + kh) : "memory");
#pragma unroll
        for (int i = 0; i < 16; i++) {
            const int kk = kh * 256 + i * 16;
            unsigned a0, a1, a2, a3r;
            const unsigned ad = sAb + ((((wm * 16 + (lane & 15)) * PA) + kk + (lane >> 4) * 8) << 1);
            asm volatile("ldmatrix.sync.aligned.m8n8.x4.shared.b16 {%0,%1,%2,%3}, [%4];"
                : "=r"(a0), "=r"(a1), "=r"(a2), "=r"(a3r) : "r"(ad));
#define MMA1(CC, B0, B1) \
            asm volatile("mma.sync.aligned.m16n8k16.row.col.f32.bf16.bf16.f32 " \
                "{%0,%1,%2,%3}, {%4,%5,%6,%7}, {%8,%9}, {%0,%1,%2,%3};" \
                : "+f"(CC[0]), "+f"(CC[1]), "+f"(CC[2]), "+f"(CC[3]) \
                : "r"(a0), "r"(a1), "r"(a2), "r"(a3r), "r"(B0), "r"(B1))
            MMA1(c0, wf[i][0], wf[i][1]); MMA1(c1, wf[i][2], wf[i][3]); MMA1(c2, wf[i][4], wf[i][5]);
            if (i < 8) {
                MMA1(c0, wl[i][0], wl[i][1]); MMA1(c1, wl[i][2], wl[i][3]); MMA1(c2, wl[i][4], wl[i][5]);
            } else {
                unsigned l00, l01, l10, l11, l20, l21;
                const int g_ = lane >> 3, rr_ = lane & 7;
                const unsigned bo  = (unsigned)(((wn * 24 + (g_ >> 1) * 8 + rr_) * PW + kk + (g_ & 1) * 8) << 1);
                const unsigned bo2 = (unsigned)(((wn * 24 + 16 + rr_) * PW + kk + ((lane >> 3) & 1) * 8) << 1);
                asm volatile("ldmatrix.sync.aligned.m8n8.x4.shared.b16 {%0,%1,%2,%3}, [%4];"
                    : "=r"(l00), "=r"(l01), "=r"(l10), "=r"(l11) : "r"(sWlb + bo));
                asm volatile("ldmatrix.sync.aligned.m8n8.x2.shared.b16 {%0,%1}, [%2];"
                    : "=r"(l20), "=r"(l21) : "r"(sWlb + bo2));
                MMA1(c0, l00, l01); MMA1(c1, l10, l11); MMA1(c2, l20, l21);
            }
        }

        asm volatile("cp.async.wait_group 0;" ::: "memory");
        asm volatile("bar.sync %0, 128;" :: "r"(1 + kh) : "memory");
#pragma unroll
        for (int i = 0; i < 16; i++) {
            const int kk = kh * 256 + i * 16;
            unsigned a0, a1, a2, a3r;
            const unsigned ad = sAb + ((((wm * 16 + (lane & 15)) * PA) + 512 + kk + (lane >> 4) * 8) << 1);
            asm volatile("ldmatrix.sync.aligned.m8n8.x4.shared.b16 {%0,%1,%2,%3}, [%4];"
                : "=r"(a0), "=r"(a1), "=r"(a2), "=r"(a3r) : "r"(ad));
            MMA1(c0, wf[i][0], wf[i][1]); MMA1(c1, wf[i][2], wf[i][3]); MMA1(c2, wf[i][4], wf[i][5]);
        }

        if (kh == 1) {
            float* rp = sred + (size_t)(((warp - 4) << 5) + lane) * 13;
#pragma unroll
            for (int q = 0; q < 4; q++) {
                rp[q] = c0[q]; rp[4 + q] = c1[q]; rp[8 + q] = c2[q];
            }
        }
        __syncthreads();

        float hv[4];
        __nv_bfloat162 hp2[2], lp2[2];
        if (kh == 0) {
            const float* rp = sred + (size_t)((warp << 5) + lane) * 13;
#pragma unroll
            for (int q = 0; q < 4; q++) {
                const float gr = c0[q] + rp[q]     + ((q & 1) ? br1 : br0);
                const float gz = c1[q] + rp[4 + q] + ((q & 1) ? bz1 : bz0);
                const float gn = c2[q] + rp[8 + q] + ((q & 1) ? bn1 : bn0);
                const float2 xr = (q >> 1) ? xr1 : xr0;
                const float2 xz = (q >> 1) ? xz1 : xz0;
                const float2 xn = (q >> 1) ? xn1 : xn0;
                const float rg = fast_sig(((q & 1) ? xr.y : xr.x) + gr);
                const float zg = fast_sig(((q & 1) ? xz.y : xz.x) + gz);
                const float ng = fast_tanh(((q & 1) ? xn.y : xn.x) + rg * gn);
                hv[q] = (1.f - zg) * ng + zg * hprev[q];
                hprev[q] = hv[q];
            }
#pragma unroll
            for (int rsel = 0; rsel < 2; rsel++) {
                const float v0 = hv[rsel * 2], v1 = hv[rsel * 2 + 1];
                const __nv_bfloat16 h0 = __float2bfloat16(v0);
                const __nv_bfloat16 h1 = __float2bfloat16(v1);
                const __nv_bfloat16 l0 = __float2bfloat16(v0 - __bfloat162float(h0));
                const __nv_bfloat16 l1 = __float2bfloat16(v1 - __bfloat162float(h1));
                hp2[rsel] = __halves2bfloat162(h0, h1);
                lp2[rsel] = __halves2bfloat162(l0, l1);
                const int brow = bg * 32 + r0 + rsel * 8;
                __nv_bfloat16* dst = &g_hA[1 - p][dir][brow][k0 + kc2];
                __stcg(reinterpret_cast<unsigned*>(dst),
                       *reinterpret_cast<const unsigned*>(&hp2[rsel]));
                __stcg(reinterpret_cast<unsigned*>(dst + 512),
                       *reinterpret_cast<const unsigned*>(&lp2[rsel]));
            }
        }
        __syncthreads();
        if (tid == 0) {
            bar_tgt += 32u;
            unsigned prev;
            asm volatile("atom.acq_rel.gpu.global.add.u32 %0, [%1], 1;"
                         : "=r"(prev) : "l"(bar) : "memory");
            (void)prev;
        } else {
            bar_tgt += 32u;
        }
        if (kh == 0) {
            if (do_pool) {
#pragma unroll
                for (int q = 0; q < 4; q++) mx[q] = fmaxf(mx[q], hv[q]);
            }
            if (a3) {
#pragma unroll
                for (int rsel = 0; rsel < 2; rsel++) {
                    const int brow = bg * 32 + r0 + rsel * 8;
                    __nv_bfloat16* ad3 = a3 + ((size_t)brow * TT + t) * 2048 + dir * HH + k0 + kc2;
                    *reinterpret_cast<unsigned*>(ad3)        = *reinterpret_cast<const unsigned*>(&hp2[rsel]);
                    *reinterpret_cast<unsigned*>(ad3 + 1024) = *reinterpret_cast<const unsigned*>(&lp2[rsel]);
                }
            }
        }
    }

    if (do_pool && kh == 0) {
#pragma unroll
        for (int q = 0; q < 4; q++) {
            const int brow = bg * 32 + r0 + (q >> 1) * 8;
            g_pooled[(size_t)brow * (2 * HH) + dir * HH + k0 + kc2 + (q & 1)] = mx[q];
        }
    }
}

// ---------------- classifier head ----------------
__global__ void mlp1_kernel(const float* __restrict__ w1, const float* __restrict__ b1) {
    const int warp = (blockIdx.x * blockDim.x + threadIdx.x) >> 5;
    const int lane = threadIdx.x & 31;
    if (warp >= BB * 128) return;
    const int b = warp >> 7, j = warp & 127;
    const float* p = g_pooled + (size_t)b * 2 * HH;
    const float* w = w1 + (size_t)j * 2 * HH;
    float s = 0.f;
    for (int k = lane; k < 2 * HH; k += 32) s = fmaf(p[k], w[k], s);
#pragma unroll
    for (int o = 16; o; o >>= 1) s += __shfl_xor_sync(0xffffffffu, s, o);
    if (lane == 0) g_hid[b * 128 + j] = fmaxf(s + b1[j], 0.f);
}

__global__ void mlp2_kernel(const float* __restrict__ w2, const float* __restrict__ b2,
                            float* __restrict__ out) {
    const int t = threadIdx.x;
    if (t < BB * 2) {
        const int b = t >> 1, c = t & 1;
        float s = b2[c];
        const float* h = g_hid + b * 128;
        const float* w = w2 + c * 128;
        for (int k = 0; k < 128; k++) s = fmaf(h[k], w[k], s);
        out[t] = s;
    }
}

// ---------------- launch ----------------
extern "C" void kernel_launch(void* const* d_in, const int* in_sizes, int n_in,
                              void* d_out, int out_size) {
    const int*   x    = (const int*)d_in[0];
    const float* emb  = (const float*)d_in[1];
    const float* wih0 = (const float*)d_in[2];
    const float* whh0 = (const float*)d_in[3];
    const float* bih0 = (const float*)d_in[4];
    const float* bhh0 = (const float*)d_in[5];
    const float* wih1 = (const float*)d_in[6];
    const float* whh1 = (const float*)d_in[7];
    const float* bih1 = (const float*)d_in[8];
    const float* bhh1 = (const float*)d_in[9];
    const float* w1   = (const float*)d_in[10];
    const float* b1   = (const float*)d_in[11];
    const float* w2   = (const float*)d_in[12];
    const float* b2   = (const float*)d_in[13];

    float* xp_p = nullptr;
    __nv_bfloat16 *a3_p = nullptr, *w3_p = nullptr;
    cudaGetSymbolAddress((void**)&xp_p, g_xp);
    cudaGetSymbolAddress((void**)&a3_p, g_a3);
    cudaGetSymbolAddress((void**)&w3_p, g_w3);

    const size_t sm_tc = (size_t)(2 * 48 * PW + 32 * PA) * sizeof(__nv_bfloat16)
                       + (size_t)(128 * 13) * sizeof(float);
    cudaFuncSetAttribute(recur_tc_kernel, cudaFuncAttributeMaxDynamicSharedMemorySize, (int)sm_tc);
    const size_t sm_gemm = (size_t)8 * 128 * PKH * sizeof(__nv_bfloat16);
    cudaFuncSetAttribute(bgemm_kernel, cudaFuncAttributeMaxDynamicSharedMemorySize, (int)sm_gemm);

    // ---- layer 0 ----
    init_kernel<<<64, 256>>>();
    embed_split_kernel<<<MM, 160>>>(x, emb);
    {
        const long pw = (long)(2 * GG) * (320 / 2);
        conv_split_kernel<<<(unsigned)((pw + 255) / 256), 256>>>(wih0, w3_p, 2 * GG, EE, 320);
    }
    bgemm_kernel<<<dim3(GG / 128, MM / 128, 2), 256, sm_gemm>>>(a3_p, w3_p, bih0, xp_p, MM, GG, 320);
    // W split for layer 1
    {
        const long pw = (long)(2 * GG) * (1024 / 2);
        conv_split_kernel<<<(unsigned)((pw + 255) / 256), 256>>>(wih1, w3_p, 2 * GG, 2 * HH, 1024);
    }
    recur_tc_kernel<<<128, 256, sm_tc>>>(xp_p, whh0, bhh0, a3_p, 0);  // writes layer-1 split A

    // ---- layer 1 ----
    bgemm_kernel<<<dim3(GG / 128, MM / 128, 2), 256, sm_gemm>>>(a3_p, w3_p, bih1, xp_p, MM, GG, 1024);
    init_kernel<<<64, 256>>>();
    recur_tc_kernel<<<128, 256, sm_tc>>>(xp_p, whh1, bhh1, nullptr, 1);

    // ---- head ----
    mlp1_kernel<<<(BB * 128 * 32) / 256, 256>>>(w1, b1);
    mlp2_kernel<<<1, 128>>>(w2, b2, (float*)d_out);
}